// round 1
// baseline (speedup 1.0000x reference)
#include <cuda_runtime.h>

#define K_DIM   5120
#define E_DIM   5120
#define N_NODES 27
#define HD      1280
#define KT      256
#define M_TILE  32
#define QKV_STRIDE 28

// ---- scratch (no allocations allowed) ----
__device__ float g_qkvT[15360 * QKV_STRIDE];   // qkv transposed: [3E][28]
__device__ float g_o[N_NODES * E_DIM];         // attention output [27][5120]
__device__ float g_colrow[54];                 // col[0..26], row[27..53]

union F2U64 { float2 f; unsigned long long u; };

static __device__ __forceinline__ unsigned long long pack2f(float a) {
    unsigned long long r;
    asm("mov.b64 %0, {%1, %1};" : "=l"(r) : "f"(a));
    return r;
}
static __device__ __forceinline__ unsigned long long ffma2(
    unsigned long long a, unsigned long long b, unsigned long long c) {
    unsigned long long d;
    asm("fma.rn.f32x2 %0, %1, %2, %3;" : "=l"(d) : "l"(a), "l"(b), "l"(c));
    return d;
}

// =====================================================================
// Skinny GEMM: out[n][m] = sum_k X[n][k] * W[m][k] + bias[m]
//   mode 0: X given, write g_qkvT[m*28 + n]           (qkv projection)
//   mode 1: X = g_o,  write out[n*E_DIM + m] * hw     (out projection)
// Block: 256 threads, 8 warps x 4 rows = 32 weight rows per block.
// =====================================================================
__global__ __launch_bounds__(256, 1)
void gemm_skinny(const float* __restrict__ Xin, const float* __restrict__ W,
                 const float* __restrict__ bias, float* __restrict__ out,
                 int mode, const int* __restrict__ lh_ptr)
{
    __shared__ unsigned long long sx[14 * KT];   // n-pairs of x, [n2][k]

    const float* __restrict__ X = (mode == 0) ? Xin : g_o;

    float hw = 1.0f;
    if (mode == 1) {
        int iv = *lh_ptr;
        float f = (iv > 0 && iv < 100000000) ? (float)iv : __int_as_float(iv);
        hw = fminf(fmaxf(f * 0.001f, 0.1f), 1.0f);
    }

    const int tid  = threadIdx.x;
    const int lane = tid & 31;
    const int wid  = tid >> 5;
    const int mbase = blockIdx.x * M_TILE + wid * 4;

    unsigned long long acc[4][14];
    #pragma unroll
    for (int m = 0; m < 4; m++)
        #pragma unroll
        for (int n2 = 0; n2 < 14; n2++) acc[m][n2] = 0ull;

    for (int kt = 0; kt < K_DIM; kt += KT) {
        __syncthreads();
        // stage x tile as n-pairs: sx[n2][k] = (x[2n2][k], x[2n2+1][k])
        #pragma unroll
        for (int it = 0; it < 14; it++) {
            int idx = tid + it * 256;
            int n2 = idx >> 8;           // idx / KT
            int k  = idx & (KT - 1);
            F2U64 t;
            t.f.x = X[(2 * n2) * K_DIM + kt + k];
            t.f.y = (2 * n2 + 1 < N_NODES) ? X[(2 * n2 + 1) * K_DIM + kt + k] : 0.0f;
            sx[n2 * KT + k] = t.u;
        }
        __syncthreads();

        // two half-tiles of 4 k-chunks each; prefetch weights per half
        #pragma unroll
        for (int half = 0; half < 2; half++) {
            unsigned long long wp[4][4];
            #pragma unroll
            for (int m = 0; m < 4; m++) {
                const float* wrow = W + (size_t)(mbase + m) * K_DIM + kt + half * 128 + lane;
                #pragma unroll
                for (int c = 0; c < 4; c++) wp[m][c] = pack2f(wrow[c * 32]);
            }
            #pragma unroll
            for (int c = 0; c < 4; c++) {
                int kk = half * 128 + c * 32 + lane;
                #pragma unroll
                for (int n2 = 0; n2 < 14; n2++) {
                    unsigned long long xv = sx[n2 * KT + kk];
                    #pragma unroll
                    for (int m = 0; m < 4; m++)
                        acc[m][n2] = ffma2(wp[m][c], xv, acc[m][n2]);
                }
            }
        }
    }

    // cross-lane reduction + store (lane 0)
    #pragma unroll
    for (int m = 0; m < 4; m++) {
        const int mg = mbase + m;
        const float bm = bias[mg];
        #pragma unroll
        for (int n2 = 0; n2 < 14; n2++) {
            F2U64 t; t.u = acc[m][n2];
            float vx = t.f.x, vy = t.f.y;
            #pragma unroll
            for (int off = 16; off; off >>= 1) {
                vx += __shfl_xor_sync(0xffffffffu, vx, off);
                vy += __shfl_xor_sync(0xffffffffu, vy, off);
            }
            if (lane == 0) {
                if (mode == 0) {
                    g_qkvT[mg * QKV_STRIDE + 2 * n2] = vx + bm;
                    if (2 * n2 + 1 < N_NODES)
                        g_qkvT[mg * QKV_STRIDE + 2 * n2 + 1] = vy + bm;
                } else {
                    out[(2 * n2) * E_DIM + mg] = (vx + bm) * hw;
                    if (2 * n2 + 1 < N_NODES)
                        out[(2 * n2 + 1) * E_DIM + mg] = (vy + bm) * hw;
                }
            }
        }
    }
}

// =====================================================================
// Attention: one block per (query i, head h). 256 threads.
// =====================================================================
__global__ __launch_bounds__(256)
void attn_kernel()
{
    const int i = blockIdx.x;
    const int h = blockIdx.y;
    const int tid = threadIdx.x;
    const int lane = tid & 31;

    __shared__ float s_sc[27];
    __shared__ float s_attn[27];
    if (tid < 27) s_sc[tid] = 0.0f;
    __syncthreads();

    // scores[j] = sum_c q[i][h*HD+c] * k[j][h*HD+c]
    float acc[27];
    #pragma unroll
    for (int j = 0; j < 27; j++) acc[j] = 0.0f;
    for (int c = tid; c < HD; c += 256) {
        int base = (h * HD + c) * QKV_STRIDE;
        float qv = g_qkvT[base + i];
        const float* krow = &g_qkvT[base + E_DIM * QKV_STRIDE];
        #pragma unroll
        for (int j = 0; j < 27; j++) acc[j] += qv * krow[j];
    }
    #pragma unroll
    for (int j = 0; j < 27; j++) {
        float v = acc[j];
        #pragma unroll
        for (int off = 16; off; off >>= 1) v += __shfl_xor_sync(0xffffffffu, v, off);
        if (lane == 0) atomicAdd(&s_sc[j], v);
    }
    __syncthreads();

    if (tid < 32) {
        const float scale = rsqrtf((float)HD);
        float s = (tid < 27) ? s_sc[tid] * scale : -1e30f;
        float mx = s;
        #pragma unroll
        for (int off = 16; off; off >>= 1)
            mx = fmaxf(mx, __shfl_xor_sync(0xffffffffu, mx, off));
        float e = (tid < 27) ? expf(s - mx) : 0.0f;
        float sum = e;
        #pragma unroll
        for (int off = 16; off; off >>= 1) sum += __shfl_xor_sync(0xffffffffu, sum, off);
        if (tid < 27) s_attn[tid] = e / sum;
    }
    __syncthreads();

    // o[i][h*HD+c] = sum_j attn[j] * v[j][h*HD+c]
    for (int c = tid; c < HD; c += 256) {
        const float* vrow = &g_qkvT[(2 * E_DIM + h * HD + c) * QKV_STRIDE];
        float o = 0.0f;
        #pragma unroll
        for (int j = 0; j < 27; j++) o += s_attn[j] * vrow[j];
        g_o[i * E_DIM + h * HD + c] = o;
    }
}

// =====================================================================
// Granger: 54 dot products of length E (col: node . w_n, row: hist . w_h)
// =====================================================================
__global__ __launch_bounds__(256)
void granger_dots(const float* __restrict__ node, const float* __restrict__ hist,
                  const float* __restrict__ gw)
{
    const int b = blockIdx.x;                    // 0..53
    const float* x  = (b < 27) ? node + b * E_DIM : hist + (b - 27) * E_DIM;
    const float* wv = (b < 27) ? gw + E_DIM : gw;  // col uses w_n=gw[E:], row uses w_h=gw[:E]
    const int tid = threadIdx.x;

    float s = 0.0f;
    for (int k = tid; k < E_DIM; k += 256) s += x[k] * wv[k];

    __shared__ float sred[8];
    #pragma unroll
    for (int off = 16; off; off >>= 1) s += __shfl_xor_sync(0xffffffffu, s, off);
    if ((tid & 31) == 0) sred[tid >> 5] = s;
    __syncthreads();
    if (tid < 8) {
        s = sred[tid];
        #pragma unroll
        for (int off = 4; off; off >>= 1) s += __shfl_xor_sync(0x000000ffu, s, off);
        if (tid == 0) g_colrow[b] = s;
    }
}

__global__ void adj_kernel(const float* __restrict__ gb, float* __restrict__ out)
{
    int t = threadIdx.x;
    if (t < 27 * 27) {
        int i = t / 27, j = t % 27;
        float v = 0.0f;
        if (i != j)
            v = 1.0f / (1.0f + expf(-(g_colrow[i] + g_colrow[27 + j] + gb[0])));
        out[N_NODES * E_DIM + t] = v;
    }
}

// =====================================================================
extern "C" void kernel_launch(void* const* d_in, const int* in_sizes, int n_in,
                              void* d_out, int out_size)
{
    const float* node = (const float*)d_in[0];
    const float* hist = (const float*)d_in[1];
    const float* gw   = (const float*)d_in[2];
    const float* gb   = (const float*)d_in[3];
    const float* inw  = (const float*)d_in[4];
    const float* inb  = (const float*)d_in[5];
    const float* outw = (const float*)d_in[6];
    const float* outb = (const float*)d_in[7];
    const int*   lh   = (const int*)d_in[8];
    float* out = (float*)d_out;

    granger_dots<<<54, 256>>>(node, hist, gw);
    adj_kernel<<<1, 736>>>(gb, out);

    // qkv = x @ in_proj_w^T + b   (15360 rows)
    gemm_skinny<<<15360 / M_TILE, 256>>>(node, inw, inb, nullptr, 0, lh);
    // multi-head attention
    attn_kernel<<<dim3(27, 4), 256>>>();
    // out = (o @ out_proj_w^T + b) * hw   (5120 rows)
    gemm_skinny<<<5120 / M_TILE, 256>>>(nullptr, outw, outb, out, 1, lh);
}

// round 4
// speedup vs baseline: 1.6312x; 1.6312x over previous
#include <cuda_runtime.h>
#include <cstdint>

#define K_DIM   5120
#define E_DIM   5120
#define N_NODES 27
#define HD      1280

// ---- scratch (device globals; no allocations allowed) ----
__device__ float    g_qkvT[15360 * 28];    // qkv transposed [3E][28]
__device__ float    g_o[N_NODES * E_DIM];  // attention output [27][5120]
__device__ float    g_colrow[54];
__device__ float    g_scores[4 * 729];
__device__ float    g_attn[4 * 729];
// B operand in MMA-fragment order: [k16 (320)][frag (8 = nt*2+reg)][lane (32)]
__device__ uint32_t g_bhi[320 * 256];
__device__ uint32_t g_blo[320 * 256];

static __device__ __forceinline__ float hw_from(const int* lh) {
    int iv = *lh;
    float f = (iv > 0 && iv < 100000000) ? (float)iv : __int_as_float(iv);
    return fminf(fmaxf(f * 0.001f, 0.1f), 1.0f);
}

// Split f32 pair -> bf16x2 hi (exact truncation) + bf16x2 lo (rounded remainder).
// hi low16 = f0's top bits (first element in low half, per mma frag layout).
static __device__ __forceinline__ void split_pack(float f0, float f1,
                                                  uint32_t& hi, uint32_t& lo) {
    uint32_t u0 = __float_as_uint(f0), u1 = __float_as_uint(f1);
    asm("prmt.b32 %0, %1, %2, 0x7632;" : "=r"(hi) : "r"(u0), "r"(u1));
    float l0 = f0 - __uint_as_float(u0 & 0xFFFF0000u);
    float l1 = f1 - __uint_as_float(u1 & 0xFFFF0000u);
    asm("cvt.rn.bf16x2.f32 %0, %1, %2;" : "=r"(lo) : "f"(l1), "f"(l0));
}

#define MMA_BF16(d, a, b0, b1)                                                  \
    asm volatile(                                                               \
        "mma.sync.aligned.m16n8k16.row.col.f32.bf16.bf16.f32 "                  \
        "{%0,%1,%2,%3}, {%4,%5,%6,%7}, {%8,%9}, {%0,%1,%2,%3};"                 \
        : "+f"((d)[0]), "+f"((d)[1]), "+f"((d)[2]), "+f"((d)[3])                \
        : "r"((a)[0]), "r"((a)[1]), "r"((a)[2]), "r"((a)[3]),                   \
          "r"(b0), "r"(b1))

// =====================================================================
// Prep: convert X (27 x 5120 f32, src=param or g_o) into B-fragment
// bf16 hi/lo arrays, zero-padded to n=32.
//   b-frag for m16n8k16: reg0 = X[n = nt*8 + lane>>2][k0, k0+1],
//   reg1 = [k0+8, k0+9], k0 = k16*16 + 2*(lane&3).
// =====================================================================
__global__ __launch_bounds__(256)
void prep_frags(const float* __restrict__ src_param, int use_go)
{
    const float* __restrict__ src = use_go ? g_o : src_param;
    int t = blockIdx.x * 256 + threadIdx.x;           // 0 .. 320*256-1
    int lane = t & 31;
    int f    = (t >> 5) & 7;
    int k16  = t >> 8;
    int reg  = f & 1;
    int nt   = f >> 1;
    int n    = nt * 8 + (lane >> 2);
    int k0   = k16 * 16 + reg * 8 + 2 * (lane & 3);
    float f0 = 0.0f, f1 = 0.0f;
    if (n < N_NODES) {
        f0 = src[(size_t)n * K_DIM + k0];
        f1 = src[(size_t)n * K_DIM + k0 + 1];
    }
    uint32_t hi, lo;
    split_pack(f0, f1, hi, lo);
    g_bhi[t] = hi;
    g_blo[t] = lo;
}

// =====================================================================
// Legacy-HMMA split-K GEMM:  D[m][n] = sum_k W[m][k] * X[n][k]
//   CTA: 128 threads, 4 warps x 32 rows = 128 W-rows.
//   grid.x = M/128, grid.y = K splits (klen per split).
//   mode 0: atomicAdd into g_qkvT[m*28+n]       (bias pre-seeded)
//   mode 1: atomicAdd val*hw into dst[n*E+m]    (bias*hw pre-seeded)
// =====================================================================
__global__ __launch_bounds__(128, 2)
void gemm_hmma(const float* __restrict__ W, float* __restrict__ dst,
               int mode, int klen, const int* __restrict__ lh)
{
    __shared__ uint32_t sB[2][16 * 8 * 32];   // [hi/lo][c*8+frag][lane], 32KB

    const int tid  = threadIdx.x;
    const int lane = tid & 31;
    const int wid  = tid >> 5;
    const int mbase = blockIdx.x * 128 + wid * 32;
    const int kbase = blockIdx.y * klen;
    const int kb16  = kbase >> 4;
    const int nk16  = klen >> 4;
    const int ntile = nk16 >> 4;
    const int r  = lane >> 2;
    const int t2 = (lane & 3) * 2;

    const float* wp = W + (size_t)(mbase + r) * K_DIM + kbase + t2;

    float acc[2][4][4];
    #pragma unroll
    for (int mf = 0; mf < 2; mf++)
        #pragma unroll
        for (int nt = 0; nt < 4; nt++)
            #pragma unroll
            for (int q = 0; q < 4; q++) acc[mf][nt][q] = 0.0f;

    // A stage: [mf*4 + kc*2 + rr] = W[row mbase+mf*16+rr*8+r][k16*16 + kc*8 + t2..+1]
    float2 stage[8];
    #pragma unroll
    for (int mf = 0; mf < 2; mf++)
        #pragma unroll
        for (int kc = 0; kc < 2; kc++)
            #pragma unroll
            for (int rr = 0; rr < 2; rr++)
                stage[mf * 4 + kc * 2 + rr] =
                    *(const float2*)(wp + (size_t)(mf * 16 + rr * 8) * K_DIM + kc * 8);

    #pragma unroll 1
    for (int tile = 0; tile < ntile; tile++) {
        __syncthreads();
        {   // copy 16KB hi + 16KB lo, contiguous
            const uint4* srcH = (const uint4*)(g_bhi + (size_t)(kb16 + tile * 16) * 256);
            const uint4* srcL = (const uint4*)(g_blo + (size_t)(kb16 + tile * 16) * 256);
            uint4* dH = (uint4*)sB[0];
            uint4* dL = (uint4*)sB[1];
            #pragma unroll
            for (int j = 0; j < 8; j++) {
                dH[tid + j * 128] = srcH[tid + j * 128];
                dL[tid + j * 128] = srcL[tid + j * 128];
            }
        }
        __syncthreads();

        #pragma unroll 1
        for (int c = 0; c < 16; c++) {
            // convert staged A
            uint32_t ahi[2][4], alo[2][4];
            #pragma unroll
            for (int q = 0; q < 8; q++)
                split_pack(stage[q].x, stage[q].y, ahi[q >> 2][q & 3], alo[q >> 2][q & 3]);

            // prefetch next A (overwrites stage, already consumed)
            int ii = tile * 16 + c + 1;
            if (ii < nk16) {
                #pragma unroll
                for (int mf = 0; mf < 2; mf++)
                    #pragma unroll
                    for (int kc = 0; kc < 2; kc++)
                        #pragma unroll
                        for (int rr = 0; rr < 2; rr++)
                            stage[mf * 4 + kc * 2 + rr] =
                                *(const float2*)(wp + (size_t)(mf * 16 + rr * 8) * K_DIM
                                                 + (size_t)ii * 16 + kc * 8);
            }

            // B fragments (lane-consecutive, conflict-free)
            uint32_t bh[4][2], bl[4][2];
            #pragma unroll
            for (int nt = 0; nt < 4; nt++) {
                bh[nt][0] = sB[0][(c * 8 + nt * 2 + 0) * 32 + lane];
                bh[nt][1] = sB[0][(c * 8 + nt * 2 + 1) * 32 + lane];
                bl[nt][0] = sB[1][(c * 8 + nt * 2 + 0) * 32 + lane];
                bl[nt][1] = sB[1][(c * 8 + nt * 2 + 1) * 32 + lane];
            }

            #pragma unroll
            for (int mf = 0; mf < 2; mf++)
                #pragma unroll
                for (int nt = 0; nt < 4; nt++) {
                    MMA_BF16(acc[mf][nt], ahi[mf], bh[nt][0], bh[nt][1]);
                    MMA_BF16(acc[mf][nt], ahi[mf], bl[nt][0], bl[nt][1]);
                    MMA_BF16(acc[mf][nt], alo[mf], bh[nt][0], bh[nt][1]);
                }
        }
    }

    // epilogue: d0=(m0,n0) d1=(m0,n0+1) d2=(m0+8,n0) d3=(m0+8,n0+1)
    if (mode == 0) {
        #pragma unroll
        for (int mf = 0; mf < 2; mf++) {
            int m0 = mbase + mf * 16 + r;
            #pragma unroll
            for (int nt = 0; nt < 4; nt++) {
                int n0 = nt * 8 + t2;
                if (n0 < N_NODES)     atomicAdd(&g_qkvT[m0 * 28 + n0],           acc[mf][nt][0]);
                if (n0 + 1 < N_NODES) atomicAdd(&g_qkvT[m0 * 28 + n0 + 1],       acc[mf][nt][1]);
                if (n0 < N_NODES)     atomicAdd(&g_qkvT[(m0 + 8) * 28 + n0],     acc[mf][nt][2]);
                if (n0 + 1 < N_NODES) atomicAdd(&g_qkvT[(m0 + 8) * 28 + n0 + 1], acc[mf][nt][3]);
            }
        }
    } else {
        const float hw = hw_from(lh);
        #pragma unroll
        for (int mf = 0; mf < 2; mf++) {
            int m0 = mbase + mf * 16 + r;
            #pragma unroll
            for (int nt = 0; nt < 4; nt++) {
                int n0 = nt * 8 + t2;
                if (n0 < N_NODES)     atomicAdd(&dst[(size_t)n0 * E_DIM + m0],           acc[mf][nt][0] * hw);
                if (n0 + 1 < N_NODES) atomicAdd(&dst[(size_t)(n0 + 1) * E_DIM + m0],     acc[mf][nt][1] * hw);
                if (n0 < N_NODES)     atomicAdd(&dst[(size_t)n0 * E_DIM + m0 + 8],       acc[mf][nt][2] * hw);
                if (n0 + 1 < N_NODES) atomicAdd(&dst[(size_t)(n0 + 1) * E_DIM + m0 + 8], acc[mf][nt][3] * hw);
            }
        }
    }
}

// =====================================================================
// Init: seed qkvT with in_proj bias, out with out_proj bias * hw, zero scores
// =====================================================================
__global__ __launch_bounds__(256)
void init_kernel(const float* __restrict__ inb, const float* __restrict__ outb,
                 const int* __restrict__ lh, float* __restrict__ out)
{
    const int t = blockIdx.x * 256 + threadIdx.x;
    if (t < 15360 * 27) {
        int m = t / 27, n = t - m * 27;
        g_qkvT[m * 28 + n] = inb[m];
    } else if (t < 15360 * 27 + 27 * 5120) {
        int t2 = t - 15360 * 27;
        int m = t2 % 5120;
        out[t2] = outb[m] * hw_from(lh);
    } else if (t < 15360 * 27 + 27 * 5120 + 4 * 729) {
        g_scores[t - (15360 * 27 + 27 * 5120)] = 0.0f;
    }
}

// =====================================================================
// Attention (tiled over channels, partial scores via atomics)
// =====================================================================
__global__ __launch_bounds__(256)
void attn_scores()
{
    const int ct = blockIdx.x;   // 0..9 (128-channel tile)
    const int h  = blockIdx.y;   // 0..3
    __shared__ float sq[128 * 29];
    __shared__ float sk[128 * 29];
    const int tid = threadIdx.x;

    const float* qb = g_qkvT + (size_t)(h * HD + ct * 128) * 28;
    const float* kb = g_qkvT + (size_t)(E_DIM + h * HD + ct * 128) * 28;
    for (int idx = tid; idx < 128 * 28; idx += 256) {
        int c = idx / 28, r = idx - c * 28;
        sq[c * 29 + r] = qb[idx];
        sk[c * 29 + r] = kb[idx];
    }
    __syncthreads();

    for (int t = tid; t < 729; t += 256) {
        int i = t / 27, j = t - i * 27;
        float s = 0.0f;
        #pragma unroll 8
        for (int c = 0; c < 128; c++)
            s += sq[c * 29 + i] * sk[c * 29 + j];
        atomicAdd(&g_scores[h * 729 + t], s);
    }
}

__global__ __launch_bounds__(128)
void attn_softmax()
{
    const int t = threadIdx.x;
    if (t >= 108) return;
    const int h = t / 27, i = t - h * 27;
    const float scale = rsqrtf((float)HD);
    const float* sc = g_scores + h * 729 + i * 27;
    float mx = -1e30f;
    #pragma unroll
    for (int j = 0; j < 27; j++) mx = fmaxf(mx, sc[j] * scale);
    float e[27], sum = 0.0f;
    #pragma unroll
    for (int j = 0; j < 27; j++) { e[j] = expf(sc[j] * scale - mx); sum += e[j]; }
    const float inv = 1.0f / sum;
    float* at = g_attn + h * 729 + i * 27;
    #pragma unroll
    for (int j = 0; j < 27; j++) at[j] = e[j] * inv;
}

__global__ __launch_bounds__(256)
void attn_out()
{
    const int ct = blockIdx.x;
    const int h  = blockIdx.y;
    __shared__ float sv[128 * 29];
    __shared__ float sa[729];
    const int tid = threadIdx.x;

    const float* vb = g_qkvT + (size_t)(2 * E_DIM + h * HD + ct * 128) * 28;
    for (int idx = tid; idx < 128 * 28; idx += 256) {
        int c = idx / 28, r = idx - c * 28;
        sv[c * 29 + r] = vb[idx];
    }
    for (int idx = tid; idx < 729; idx += 256) sa[idx] = g_attn[h * 729 + idx];
    __syncthreads();

    for (int f = tid; f < 27 * 128; f += 256) {
        int c = f & 127, i = f >> 7;
        float o = 0.0f;
        #pragma unroll
        for (int j = 0; j < 27; j++) o += sa[i * 27 + j] * sv[c * 29 + j];
        g_o[(size_t)i * E_DIM + h * HD + ct * 128 + c] = o;
    }
}

// =====================================================================
// Granger dots + adjacency
// =====================================================================
__global__ __launch_bounds__(256)
void granger_dots(const float* __restrict__ node, const float* __restrict__ hist,
                  const float* __restrict__ gw)
{
    const int b = blockIdx.x;  // 0..53
    const float* x  = (b < 27) ? node + (size_t)b * E_DIM : hist + (size_t)(b - 27) * E_DIM;
    const float* wv = (b < 27) ? gw + E_DIM : gw;
    const int tid = threadIdx.x;

    float s = 0.0f;
    for (int k = tid; k < E_DIM; k += 256) s += x[k] * wv[k];

    __shared__ float sred[8];
    #pragma unroll
    for (int off = 16; off; off >>= 1) s += __shfl_xor_sync(0xffffffffu, s, off);
    if ((tid & 31) == 0) sred[tid >> 5] = s;
    __syncthreads();
    if (tid < 8) {
        s = sred[tid];
        #pragma unroll
        for (int off = 4; off; off >>= 1) s += __shfl_xor_sync(0x000000ffu, s, off);
        if (tid == 0) g_colrow[b] = s;
    }
}

__global__ void adj_kernel(const float* __restrict__ gb, float* __restrict__ out)
{
    int t = threadIdx.x;
    if (t < 27 * 27) {
        int i = t / 27, j = t - i * 27;
        float v = 0.0f;
        if (i != j)
            v = 1.0f / (1.0f + expf(-(g_colrow[i] + g_colrow[27 + j] + gb[0])));
        out[N_NODES * E_DIM + t] = v;
    }
}

// =====================================================================
extern "C" void kernel_launch(void* const* d_in, const int* in_sizes, int n_in,
                              void* d_out, int out_size)
{
    const float* node = (const float*)d_in[0];
    const float* hist = (const float*)d_in[1];
    const float* gw   = (const float*)d_in[2];
    const float* gb   = (const float*)d_in[3];
    const float* inw  = (const float*)d_in[4];
    const float* inb  = (const float*)d_in[5];
    const float* outw = (const float*)d_in[6];
    const float* outb = (const float*)d_in[7];
    const int*   lh   = (const int*)d_in[8];
    float* out = (float*)d_out;

    granger_dots<<<54, 256>>>(node, hist, gw);
    adj_kernel<<<1, 736>>>(gb, out);

    const int init_elems = 15360 * 27 + 27 * 5120 + 4 * 729;
    init_kernel<<<(init_elems + 255) / 256, 256>>>(inb, outb, lh, out);

    // X -> B fragments for GEMM1
    prep_frags<<<320, 256>>>(node, 0);

    // qkv += x @ in_proj_w^T : 120 M-tiles x 2 K-splits (klen 2560)
    gemm_hmma<<<dim3(120, 2), 128>>>(inw, nullptr, 0, 2560, lh);

    attn_scores<<<dim3(10, 4), 256>>>();
    attn_softmax<<<1, 128>>>();
    attn_out<<<dim3(10, 4), 256>>>();

    // g_o -> B fragments for GEMM2
    prep_frags<<<320, 256>>>(nullptr, 1);

    // out += (o @ out_proj_w^T) * hw : 40 M-tiles x 4 K-splits (klen 1280)
    gemm_hmma<<<dim3(40, 4), 128>>>(outw, out, 1, 1280, lh);
}